// round 3
// baseline (speedup 1.0000x reference)
#include <cuda_runtime.h>

// Batched per-object 3-layer MLP — 2-launch version.
//
// KA (fused):  blocks [0, 16384)     : y1 chunks (32 rows) + release g_done[o]
//              blocks [16384, 32768) : acquire g_done[o]==8, y2 chunks (32 rows),
//                                      partial W3 dot -> atomicAdd g_acc[o]
// KB (tiny):   out[o] = sigmoid(g_acc[o] + b3[o]); reset g_done for graph replay.
//
// Pure HBM-streaming: every weight byte read exactly once, coalesced float4,
// evict-first (.cs). No y2 staging traffic at all.

#define N_OBJ_  2048
#define IN_DIM_ 128
#define MID_    256
#define K1_BLOCKS_ (N_OBJ_ * 8)

__device__ float    g_y1[N_OBJ_ * MID_];
__device__ float    g_acc[N_OBJ_];
__device__ unsigned g_done[N_OBJ_];   // zero-initialized; KB resets each run

__device__ __forceinline__ float warp_sum(float v) {
#pragma unroll
    for (int off = 16; off > 0; off >>= 1)
        v += __shfl_xor_sync(0xffffffffu, v, off);
    return v;
}

__device__ __forceinline__ float sigmoidf_(float t) {
    return 1.0f / (1.0f + __expf(-t));
}

__global__ __launch_bounds__(128, 16)
void ka_fused(const float* __restrict__ x,
              const float* __restrict__ W1,
              const float* __restrict__ b1,
              const float* __restrict__ W2,
              const float* __restrict__ b2,
              const float* __restrict__ W3)
{
    const int warp = threadIdx.x >> 5;
    const int lane = threadIdx.x & 31;

    if (blockIdx.x < K1_BLOCKS_) {
        // ---------------- K1: 32 rows of y1 for object o ----------------
        const int o     = blockIdx.x >> 3;
        const int chunk = blockIdx.x & 7;

        const float4 xv =
            reinterpret_cast<const float4*>(x + (size_t)o * IN_DIM_)[lane];
        const float* W1o = W1 + (size_t)o * MID_ * IN_DIM_;
        const int row0 = chunk * 32 + warp * 8;

#pragma unroll
        for (int j = 0; j < 8; ++j) {
            const int row = row0 + j;
            const float4 w = __ldcs(
                reinterpret_cast<const float4*>(W1o + (size_t)row * IN_DIM_) + lane);
            float s = fmaf(w.x, xv.x, fmaf(w.y, xv.y, fmaf(w.z, xv.z, w.w * xv.w)));
            s = warp_sum(s);
            if (lane == 0)
                g_y1[o * MID_ + row] = s + b1[o * MID_ + row];
        }
        // chunk 0 also re-zeroes the accumulator for this replay
        if (chunk == 0 && threadIdx.x == 0) g_acc[o] = 0.0f;

        // release: make y1 (and acc zero) visible, then bump counter
        __syncthreads();
        if (threadIdx.x == 0) {
            __threadfence();
            atomicAdd(&g_done[o], 1u);
        }
    } else {
        // ------- K2: 32 rows of y2 + partial W3 dot for object o --------
        const int bid2  = blockIdx.x - K1_BLOCKS_;
        const int o     = bid2 >> 3;
        const int chunk = bid2 & 7;

        // acquire: wait for all 8 y1 chunks of this object
        if (threadIdx.x == 0) {
            while (*(volatile unsigned*)&g_done[o] < 8u) { }
            __threadfence();
        }
        __syncthreads();

        const float4* y1v = reinterpret_cast<const float4*>(g_y1 + o * MID_);
        const float4 ya = y1v[lane];
        const float4 yb = y1v[32 + lane];

        const float* W2o = W2 + (size_t)o * MID_ * MID_;
        const float* W3o = W3 + (size_t)o * MID_;
        const int row0 = chunk * 32 + warp * 8;

        float p = 0.0f;   // lane-0 partial of W3 . y2 over this warp's rows
#pragma unroll
        for (int j = 0; j < 8; ++j) {
            const int row = row0 + j;
            const float4* wr =
                reinterpret_cast<const float4*>(W2o + (size_t)row * MID_);
            const float4 wa = __ldcs(wr + lane);
            const float4 wb = __ldcs(wr + 32 + lane);
            float s = fmaf(wa.x, ya.x, fmaf(wa.y, ya.y,
                      fmaf(wa.z, ya.z, fmaf(wa.w, ya.w,
                      fmaf(wb.x, yb.x, fmaf(wb.y, yb.y,
                      fmaf(wb.z, yb.z, wb.w * yb.w)))))));
            s = warp_sum(s);
            if (lane == 0) {
                const float y2v_ = sigmoidf_(s + b2[o * MID_ + row]);
                p = fmaf(W3o[row], y2v_, p);
            }
        }

        __shared__ float sp[4];
        if (lane == 0) sp[warp] = p;
        __syncthreads();
        if (threadIdx.x == 0)
            atomicAdd(&g_acc[o], sp[0] + sp[1] + sp[2] + sp[3]);
    }
}

__global__ __launch_bounds__(256)
void kb_final(const float* __restrict__ b3, float* __restrict__ out)
{
    const int o = blockIdx.x * 256 + threadIdx.x;
    out[o] = sigmoidf_(g_acc[o] + b3[o]);
    g_done[o] = 0u;   // reset for next graph replay
}

extern "C" void kernel_launch(void* const* d_in, const int* in_sizes, int n_in,
                              void* d_out, int out_size)
{
    const float* x  = (const float*)d_in[0];
    const float* W1 = (const float*)d_in[1];
    const float* b1 = (const float*)d_in[2];
    const float* W2 = (const float*)d_in[3];
    const float* b2 = (const float*)d_in[4];
    const float* W3 = (const float*)d_in[5];
    const float* b3 = (const float*)d_in[6];
    float* out = (float*)d_out;

    ka_fused<<<2 * K1_BLOCKS_, 128>>>(x, W1, b1, W2, b2, W3);
    kb_final<<<N_OBJ_ / 256, 256>>>(b3, out);
}